// round 14
// baseline (speedup 1.0000x reference)
#include <cuda_runtime.h>
#include <cuda_fp16.h>
#include <cstdint>

// ---------------------------------------------------------------------------
// EdgeUpdate, R13.
//   = R11 (best: fp16 mma.sync, 4 m-groups x 3-way k-split, group-local
//   prefetch + named barriers, scalar LDS B fragments) with the d-loop
//   processed TWO chunks per barrier over a 6-deep cp.async ring:
//   half the barriers/waits, two independent MMA streams per window,
//   f-scalars loaded as float2 pairs.  (ldmatrix experiment reverted.)
// ---------------------------------------------------------------------------

constexpr int AP_STR  = 76;                 // APu: 128 x 76 u32 (kp 0..71)
constexpr int BP_W    = 9728;               // u32 offset of B ring
constexpr int BP_BUF  = 5184;               // 72*72 u32 per buffer
constexpr int BP_STR  = 72;
constexpr int W1H_STR = 136;
constexpr int XP_STR  = 36;
constexpr int FS_W    = 40832;  constexpr int F_STR = 82;   // 128 x 82 floats
constexpr int B1_W    = 51328;
constexpr int GB_W    = 51456;
constexpr int SMEM_W  = 51584;              // 206336 bytes

// k-pair-packed fp16 W2aug chunks: w2h[d][kp][n], kp=0..71 (k=2kp,2kp+1)
__device__ unsigned w2h[80 * 72 * 64];

__device__ __forceinline__ void mma_f16(float* c, const unsigned* a,
                                        unsigned b0, unsigned b1) {
    asm volatile(
        "mma.sync.aligned.m16n8k16.row.col.f32.f16.f16.f32 "
        "{%0,%1,%2,%3}, {%4,%5,%6,%7}, {%8,%9}, {%0,%1,%2,%3};"
        : "+f"(c[0]), "+f"(c[1]), "+f"(c[2]), "+f"(c[3])
        : "r"(a[0]), "r"(a[1]), "r"(a[2]), "r"(a[3]), "r"(b0), "r"(b1));
}

__device__ __forceinline__ void mma_f16_z(float* d, const unsigned* a,
                                          unsigned b0, unsigned b1) {
    asm volatile(
        "mma.sync.aligned.m16n8k16.row.col.f32.f16.f16.f32 "
        "{%0,%1,%2,%3}, {%4,%5,%6,%7}, {%8,%9}, {%10,%11,%12,%13};"
        : "=f"(d[0]), "=f"(d[1]), "=f"(d[2]), "=f"(d[3])
        : "r"(a[0]), "r"(a[1]), "r"(a[2]), "r"(a[3]), "r"(b0), "r"(b1),
          "f"(0.f), "f"(0.f), "f"(0.f), "f"(0.f));
}

__device__ __forceinline__ void cp_async16(void* smem_dst, const void* gsrc) {
    unsigned saddr = (unsigned)__cvta_generic_to_shared(smem_dst);
    asm volatile("cp.async.cg.shared.global [%0], [%1], 16;" :: "r"(saddr), "l"(gsrc));
}

__device__ __forceinline__ unsigned packh2(float lo, float hi) {
    __half2 h = __floats2half2_rn(lo, hi);
    return *reinterpret_cast<unsigned*>(&h);
}

__global__ void pack_w2(const float* __restrict__ W2, const float* __restrict__ b2) {
    const int i = blockIdx.x * 256 + threadIdx.x;
    if (i >= 80 * 72 * 64) return;
    const int n  = i & 63;
    const int kp = (i >> 6) % 72;
    const int d  = i / (72 * 64);
    const int col = d * 64 + n;
    const int k0 = 2 * kp, k1 = 2 * kp + 1;
    const float lo = (k0 < 128) ? W2[(size_t)k0 * 5120 + col] : (k0 == 128 ? b2[col] : 0.f);
    const float hi = (k1 < 128) ? W2[(size_t)k1 * 5120 + col] : (k1 == 128 ? b2[col] : 0.f);
    w2h[(size_t)d * 4608 + kp * 64 + n] = packh2(lo, hi);
}

__global__ __launch_bounds__(384, 1)
void edge_kernel(const float* __restrict__ res,
                 const float* __restrict__ xf,
                 const float* __restrict__ esh,
                 const float* __restrict__ W1,
                 const float* __restrict__ b1,
                 const float* __restrict__ gamma,
                 const float* __restrict__ beta,
                 const int* __restrict__ ei,
                 float* __restrict__ out,
                 int E)
{
    extern __shared__ float smem[];
    unsigned* APu = (unsigned*)smem;            // k-pair-packed fp16 H
    unsigned* BPu = (unsigned*)smem + BP_W;     // 6-deep W2-chunk ring
    unsigned* W1h = BPu + 2 * BP_BUF;           // aliased into ring slots 2,3
    unsigned* Xp  = W1h + 32 * W1H_STR;
    float*    fs  = smem + FS_W;
    float*    b1s = smem + B1_W;
    float*    gs  = smem + GB_W;
    float*    bs  = gs + 64;

    const int tid  = threadIdx.x;
    const int lane = tid & 31;
    const int w    = tid >> 5;        // warp 0..11
    const int mg   = w & 3;           // m-group (32 rows)
    const int kt   = w >> 2;          // k-split third (0,1,2)
    const int g    = lane >> 2;
    const int q    = lane & 3;
    const int e0   = blockIdx.x * 128;

    // ---- group-local prefetch: group kt owns B rows [24kt, 24kt+24) --------
    auto prefetch = [&](int d) {
        unsigned* dstb = BPu + (d % 6) * BP_BUF + kt * 24 * BP_STR;
        const unsigned* src = w2h + (size_t)d * 4608 + kt * 24 * 64;
        const int tg = tid & 127;
        #pragma unroll
        for (int t = tg; t < 384; t += 128) {            // 24 rows x 16 segs
            const int row = t >> 4, seg = t & 15;
            cp_async16(dstb + row * BP_STR + seg * 4, src + row * 64 + seg * 4);
        }
        asm volatile("cp.async.commit_group;");
    };
    prefetch(0);
    prefetch(1);

    // ---- pack W1 -> W1h (k-pair fp16), X -> Xp ------------------------------
    for (int idx = tid; idx < 4096; idx += 384) {
        const int kp = idx >> 7, n = idx & 127;
        W1h[kp * W1H_STR + n] = packh2(W1[(size_t)(2 * kp) * 128 + n],
                                       W1[(size_t)(2 * kp + 1) * 128 + n]);
    }
    for (int idx = tid; idx < 4096; idx += 384) {
        const int row = idx >> 5, kp = idx & 31;
        const float2 v = *(const float2*)(xf + (size_t)(e0 + row) * 64 + 2 * kp);
        Xp[row * XP_STR + kp] = packh2(v.x, v.y);
    }
    if (tid < 128) b1s[tid] = b1[tid];
    if (tid < 64) { gs[tid] = gamma[tid]; bs[tid] = beta[tid]; }

    // ---- feats gather, pre-scaled by 1/sqrt(80) ----------------------------
    if (tid < 128) {
        const int e  = e0 + tid;
        const int di = ei[e];
        const int si = ei[E + e];
        const float* sr = res + (size_t)si * 56;
        const float* dr = res + (size_t)di * 56;
        const float inv80 = 0.111803398874989485f;            // 1/sqrt(80)
        const float i380  = 0.111803398874989485f * 0.57735026918962576f;
        const float s0 = esh[e * 4 + 0] * inv80;
        const float sx = esh[e * 4 + 1] * i380;
        const float sy = esh[e * 4 + 2] * i380;
        const float sz = esh[e * 4 + 3] * i380;
        float* fr = fs + tid * F_STR;
        #pragma unroll
        for (int j = 0; j < 32; j++) { fr[j] = sr[j] * s0; fr[32 + j] = dr[j] * s0; }
        #pragma unroll
        for (int m = 0; m < 8; m++) {
            fr[64 + m] = sr[32 + 3*m] * sx + sr[33 + 3*m] * sy + sr[34 + 3*m] * sz;
            fr[72 + m] = dr[32 + 3*m] * sx + dr[33 + 3*m] * sy + dr[34 + 3*m] * sz;
        }
    }
    __syncthreads();

    // ---- phase 1: H = relu(X @ W1 + b1) via MMA, pack into APu -------------
    if (w < 8) {
        const int mg2 = w & 3, nh = w >> 2;
        float Gp[2][8][4];
        #pragma unroll
        for (int ks = 0; ks < 4; ks++) {
            unsigned pa[2][4];
            #pragma unroll
            for (int mt = 0; mt < 2; mt++) {
                const int r0 = mg2 * 32 + mt * 16;
                pa[mt][0] = Xp[(r0 + g)     * XP_STR + ks * 8 + q];
                pa[mt][1] = Xp[(r0 + 8 + g) * XP_STR + ks * 8 + q];
                pa[mt][2] = Xp[(r0 + g)     * XP_STR + ks * 8 + 4 + q];
                pa[mt][3] = Xp[(r0 + 8 + g) * XP_STR + ks * 8 + 4 + q];
            }
            #pragma unroll
            for (int nt = 0; nt < 8; nt++) {
                const int n = nh * 64 + nt * 8 + g;
                const unsigned b0 = W1h[(ks * 8 + q)     * W1H_STR + n];
                const unsigned b1v = W1h[(ks * 8 + 4 + q) * W1H_STR + n];
                if (ks == 0) {
                    mma_f16_z(Gp[0][nt], pa[0], b0, b1v);
                    mma_f16_z(Gp[1][nt], pa[1], b0, b1v);
                } else {
                    mma_f16(Gp[0][nt], pa[0], b0, b1v);
                    mma_f16(Gp[1][nt], pa[1], b0, b1v);
                }
            }
        }
        #pragma unroll
        for (int mt = 0; mt < 2; mt++) {
            const int r0 = mg2 * 32 + mt * 16;
            #pragma unroll
            for (int nt = 0; nt < 8; nt++) {
                const int col = nh * 64 + nt * 8 + 2 * q;
                const int kp  = nh * 32 + nt * 4 + q;
                const float bl = b1s[col], bh = b1s[col + 1];
                APu[(r0 + g) * AP_STR + kp] =
                    packh2(fmaxf(Gp[mt][nt][0] + bl, 0.f),
                           fmaxf(Gp[mt][nt][1] + bh, 0.f));
                APu[(r0 + 8 + g) * AP_STR + kp] =
                    packh2(fmaxf(Gp[mt][nt][2] + bl, 0.f),
                           fmaxf(Gp[mt][nt][3] + bh, 0.f));
            }
        }
    }
    if (tid < 128) {     // augmented cols: kp64 = (1,0) for b2 row; kp65..71 = 0
        APu[tid * AP_STR + 64] = 0x00003C00u;
        #pragma unroll
        for (int kp = 65; kp < 72; kp++) APu[tid * AP_STR + kp] = 0u;
    }
    __syncthreads();     // APu ready; W1h/Xp (ring slots 2,3) dead from here

    prefetch(2);
    prefetch(3);

    // ---- load persistent A fragments (H, unscaled) -------------------------
    const int rb0 = mg * 32;
    unsigned afr[2][3][4];
    #pragma unroll
    for (int mt = 0; mt < 2; mt++)
        #pragma unroll
        for (int ks = 0; ks < 3; ks++) {
            const int K8 = (kt * 3 + ks) * 8;
            const int r0 = rb0 + mt * 16;
            afr[mt][ks][0] = APu[(r0 + g)     * AP_STR + K8 + q];
            afr[mt][ks][1] = APu[(r0 + 8 + g) * AP_STR + K8 + q];
            afr[mt][ks][2] = APu[(r0 + g)     * AP_STR + K8 + 4 + q];
            afr[mt][ks][3] = APu[(r0 + 8 + g) * AP_STR + K8 + 4 + q];
        }

    float acc[2][8][4];
    #pragma unroll
    for (int mt = 0; mt < 2; mt++)
        #pragma unroll
        for (int nt = 0; nt < 8; nt++)
            #pragma unroll
            for (int i = 0; i < 4; i++) acc[mt][nt][i] = 0.f;

    const int rowA0 = rb0 + g;
    const int barid = 1 + kt;

    // one chunk's MMA burst (R11 inner loop, unchanged)
    auto consume = [&](const unsigned* Bb, float f00, float f01,
                       float f10, float f11) {
        #pragma unroll
        for (int nt = 0; nt < 8; nt++) {
            const int n = nt * 8 + g;
            float G0[4], G1[4];
            {
                const unsigned b0 = Bb[(kt * 24 + q)     * BP_STR + n];
                const unsigned b1 = Bb[(kt * 24 + 4 + q) * BP_STR + n];
                mma_f16_z(G0, afr[0][0], b0, b1);
                mma_f16_z(G1, afr[1][0], b0, b1);
            }
            {
                const unsigned b0 = Bb[(kt * 24 + 8 + q)  * BP_STR + n];
                const unsigned b1 = Bb[(kt * 24 + 12 + q) * BP_STR + n];
                mma_f16(G0, afr[0][1], b0, b1);
                mma_f16(G1, afr[1][1], b0, b1);
            }
            {
                const unsigned b0 = Bb[(kt * 24 + 16 + q) * BP_STR + n];
                const unsigned b1 = Bb[(kt * 24 + 20 + q) * BP_STR + n];
                mma_f16(G0, afr[0][2], b0, b1);
                mma_f16(G1, afr[1][2], b0, b1);
            }
            acc[0][nt][0] = fmaf(f00, G0[0], acc[0][nt][0]);
            acc[0][nt][1] = fmaf(f00, G0[1], acc[0][nt][1]);
            acc[0][nt][2] = fmaf(f01, G0[2], acc[0][nt][2]);
            acc[0][nt][3] = fmaf(f01, G0[3], acc[0][nt][3]);
            acc[1][nt][0] = fmaf(f10, G1[0], acc[1][nt][0]);
            acc[1][nt][1] = fmaf(f10, G1[1], acc[1][nt][1]);
            acc[1][nt][2] = fmaf(f11, G1[2], acc[1][nt][2]);
            acc[1][nt][3] = fmaf(f11, G1[3], acc[1][nt][3]);
        }
    };

    // ---- main loop: 40 windows of 2 d-chunks each --------------------------
    #pragma unroll 1
    for (int d = 0; d < 80; d += 2) {
        if (d < 76) {
            prefetch(d + 4);
            prefetch(d + 5);
            asm volatile("cp.async.wait_group 4;");
        } else if (d == 76) {
            asm volatile("cp.async.wait_group 2;");
        } else {
            asm volatile("cp.async.wait_group 0;");
        }
        asm volatile("bar.sync %0, %1;" :: "r"(barid), "r"(128) : "memory");

        // f pairs for (d, d+1): adjacent in fs, 8B-aligned (d even, F_STR even)
        const float2 fA = *(const float2*)(fs + (rowA0)      * F_STR + d);
        const float2 fB = *(const float2*)(fs + (rowA0 + 8)  * F_STR + d);
        const float2 fC = *(const float2*)(fs + (rowA0 + 16) * F_STR + d);
        const float2 fD = *(const float2*)(fs + (rowA0 + 24) * F_STR + d);

        consume(BPu + (d % 6) * BP_BUF,       fA.x, fB.x, fC.x, fD.x);
        consume(BPu + ((d + 1) % 6) * BP_BUF, fA.y, fB.y, fC.y, fD.y);
    }
    __syncthreads();

    // ---- cross-warp (3-way k-split) reduction ------------------------------
    float* red = (float*)BPu;                    // ring dead
    if (kt >= 1) {
        float* dst = red + (kt - 1) * 8192 + mg * 2048;
        #pragma unroll
        for (int mt = 0; mt < 2; mt++)
            #pragma unroll
            for (int nt = 0; nt < 8; nt++)
                #pragma unroll
                for (int i = 0; i < 4; i++)
                    dst[(mt * 32 + nt * 4 + i) * 32 + lane] = acc[mt][nt][i];
    }
    __syncthreads();
    if (kt == 0) {
        const float* s1 = red + mg * 2048;
        const float* s2 = red + 8192 + mg * 2048;
        #pragma unroll
        for (int mt = 0; mt < 2; mt++)
            #pragma unroll
            for (int nt = 0; nt < 8; nt++)
                #pragma unroll
                for (int i = 0; i < 4; i++) {
                    const int off = (mt * 32 + nt * 4 + i) * 32 + lane;
                    acc[mt][nt][i] += s1[off] + s2[off];
                }

        // ---- epilogue: residual + LayerNorm (feats pre-scaled) -------------
        #pragma unroll
        for (int mt = 0; mt < 2; mt++) {
            #pragma unroll
            for (int par = 0; par < 2; par++) {
                const int r = rowA0 + mt * 16 + par * 8;
                const size_t rg = (size_t)(e0 + r);
                const float* xrow = xf + rg * 64;
                float v[16];
                float s = 0.f, ss = 0.f;
                #pragma unroll
                for (int nt = 0; nt < 8; nt++) {
                    const int h = nt * 8 + 2 * q;
                    const float2 xv = *(const float2*)(xrow + h);
                    const float v0 = acc[mt][nt][par * 2 + 0] + xv.x;
                    const float v1 = acc[mt][nt][par * 2 + 1] + xv.y;
                    v[nt * 2] = v0; v[nt * 2 + 1] = v1;
                    s += v0 + v1;
                    ss += v0 * v0 + v1 * v1;
                }
                s  += __shfl_xor_sync(0xffffffffu, s, 1);
                s  += __shfl_xor_sync(0xffffffffu, s, 2);
                ss += __shfl_xor_sync(0xffffffffu, ss, 1);
                ss += __shfl_xor_sync(0xffffffffu, ss, 2);
                const float mean = s * (1.f / 64.f);
                const float var  = ss * (1.f / 64.f) - mean * mean;
                const float rstd = rsqrtf(var + 1e-5f);
                float* orow = out + rg * 64;
                #pragma unroll
                for (int nt = 0; nt < 8; nt++) {
                    const int h = nt * 8 + 2 * q;
                    float2 o;
                    o.x = (v[nt * 2]     - mean) * rstd * gs[h]     + bs[h];
                    o.y = (v[nt * 2 + 1] - mean) * rstd * gs[h + 1] + bs[h + 1];
                    *(float2*)(orow + h) = o;
                }
            }
        }
    }
}

extern "C" void kernel_launch(void* const* d_in, const int* in_sizes, int n_in,
                              void* d_out, int out_size)
{
    const float* res   = (const float*)d_in[0];
    const float* xf    = (const float*)d_in[1];
    const float* esh   = (const float*)d_in[2];
    const float* W1    = (const float*)d_in[3];
    const float* b1    = (const float*)d_in[4];
    const float* W2    = (const float*)d_in[5];
    const float* b2    = (const float*)d_in[6];
    const float* gamma = (const float*)d_in[7];
    const float* beta  = (const float*)d_in[8];
    const int*   ei    = (const int*)d_in[9];   // int32: JAX x64-disabled

    const int E = in_sizes[1] / 64;             // edge_features is (E, 64)
    const size_t smem_bytes = SMEM_W * sizeof(float);

    cudaFuncSetAttribute(edge_kernel, cudaFuncAttributeMaxDynamicSharedMemorySize,
                         (int)smem_bytes);

    pack_w2<<<(80 * 72 * 64 + 255) / 256, 256>>>(W2, b2);
    edge_kernel<<<E / 128, 384, smem_bytes>>>(res, xf, esh, W1, b1,
                                              gamma, beta, ei, (float*)d_out, E);
}

// round 17
// speedup vs baseline: 1.1503x; 1.1503x over previous
#include <cuda_runtime.h>
#include <cuda_fp16.h>
#include <cstdint>

// ---------------------------------------------------------------------------
// EdgeUpdate, R14 = R11 (best) + de-phased k-groups.
//   fp16 mma.sync, 384 threads, 4 m-groups x 3-way k-split, group-local
//   prefetch + named barriers, 4-deep ring.  NEW: group kt processes the 80
//   W2 chunks in rotated order starting at d0 = kt*28, so the 3 warps that
//   share each SMSP are always at unrelated pipeline phases (LDS bursts of
//   one overlap MMA bursts of another).  acc is order-independent.
// ---------------------------------------------------------------------------

constexpr int AP_STR  = 76;                 // APu: 128 x 76 u32 (kp 0..71)
constexpr int BP_W    = 9728;               // u32 offset of B ring
constexpr int BP_BUF  = 5184;               // 72*72 u32 per buffer
constexpr int BP_STR  = 72;
constexpr int W1H_STR = 136;
constexpr int XP_STR  = 36;
constexpr int FS_W    = 30464;  constexpr int F_STR = 81;   // 128 x 81 floats
constexpr int B1_W    = 40832;
constexpr int GB_W    = 40960;
constexpr int SMEM_W  = 41088;              // 164352 bytes

// k-pair-packed fp16 W2aug chunks: w2h[d][kp][n], kp=0..71 (k=2kp,2kp+1)
__device__ unsigned w2h[80 * 72 * 64];

__device__ __forceinline__ void mma_f16(float* c, const unsigned* a,
                                        unsigned b0, unsigned b1) {
    asm volatile(
        "mma.sync.aligned.m16n8k16.row.col.f32.f16.f16.f32 "
        "{%0,%1,%2,%3}, {%4,%5,%6,%7}, {%8,%9}, {%0,%1,%2,%3};"
        : "+f"(c[0]), "+f"(c[1]), "+f"(c[2]), "+f"(c[3])
        : "r"(a[0]), "r"(a[1]), "r"(a[2]), "r"(a[3]), "r"(b0), "r"(b1));
}

__device__ __forceinline__ void mma_f16_z(float* d, const unsigned* a,
                                          unsigned b0, unsigned b1) {
    asm volatile(
        "mma.sync.aligned.m16n8k16.row.col.f32.f16.f16.f32 "
        "{%0,%1,%2,%3}, {%4,%5,%6,%7}, {%8,%9}, {%10,%11,%12,%13};"
        : "=f"(d[0]), "=f"(d[1]), "=f"(d[2]), "=f"(d[3])
        : "r"(a[0]), "r"(a[1]), "r"(a[2]), "r"(a[3]), "r"(b0), "r"(b1),
          "f"(0.f), "f"(0.f), "f"(0.f), "f"(0.f));
}

__device__ __forceinline__ void cp_async16(void* smem_dst, const void* gsrc) {
    unsigned saddr = (unsigned)__cvta_generic_to_shared(smem_dst);
    asm volatile("cp.async.cg.shared.global [%0], [%1], 16;" :: "r"(saddr), "l"(gsrc));
}

__device__ __forceinline__ unsigned packh2(float lo, float hi) {
    __half2 h = __floats2half2_rn(lo, hi);
    return *reinterpret_cast<unsigned*>(&h);
}

__global__ void pack_w2(const float* __restrict__ W2, const float* __restrict__ b2) {
    const int i = blockIdx.x * 256 + threadIdx.x;
    if (i >= 80 * 72 * 64) return;
    const int n  = i & 63;
    const int kp = (i >> 6) % 72;
    const int d  = i / (72 * 64);
    const int col = d * 64 + n;
    const int k0 = 2 * kp, k1 = 2 * kp + 1;
    const float lo = (k0 < 128) ? W2[(size_t)k0 * 5120 + col] : (k0 == 128 ? b2[col] : 0.f);
    const float hi = (k1 < 128) ? W2[(size_t)k1 * 5120 + col] : (k1 == 128 ? b2[col] : 0.f);
    w2h[(size_t)d * 4608 + kp * 64 + n] = packh2(lo, hi);
}

__global__ __launch_bounds__(384, 1)
void edge_kernel(const float* __restrict__ res,
                 const float* __restrict__ xf,
                 const float* __restrict__ esh,
                 const float* __restrict__ W1,
                 const float* __restrict__ b1,
                 const float* __restrict__ gamma,
                 const float* __restrict__ beta,
                 const int* __restrict__ ei,
                 float* __restrict__ out,
                 int E)
{
    extern __shared__ float smem[];
    unsigned* APu = (unsigned*)smem;            // k-pair-packed fp16 H
    unsigned* BPu = (unsigned*)smem + BP_W;     // 4-deep W2-chunk ring
    unsigned* W1h = BPu + 2 * BP_BUF;           // aliased into ring slots 2,3
    unsigned* Xp  = W1h + 32 * W1H_STR;
    float*    fs  = smem + FS_W;
    float*    b1s = smem + B1_W;
    float*    gs  = smem + GB_W;
    float*    bs  = gs + 64;

    const int tid  = threadIdx.x;
    const int lane = tid & 31;
    const int w    = tid >> 5;        // warp 0..11
    const int mg   = w & 3;           // m-group (32 rows)
    const int kt   = w >> 2;          // k-split third (0,1,2)
    const int g    = lane >> 2;
    const int q    = lane & 3;
    const int e0   = blockIdx.x * 128;
    const int d0   = kt * 28;         // group phase offset: 0 / 28 / 56 (≡0 mod 4)

    // ---- group-local prefetch: group kt owns B rows [24kt, 24kt+24) --------
    auto prefetch = [&](int d) {      // d already reduced mod 80 by caller
        unsigned* dstb = BPu + (d & 3) * BP_BUF + kt * 24 * BP_STR;
        const unsigned* src = w2h + (size_t)d * 4608 + kt * 24 * 64;
        const int tg = tid & 127;
        #pragma unroll
        for (int t = tg; t < 384; t += 128) {            // 24 rows x 16 segs
            const int row = t >> 4, seg = t & 15;
            cp_async16(dstb + row * BP_STR + seg * 4, src + row * 64 + seg * 4);
        }
        asm volatile("cp.async.commit_group;");
    };
    prefetch(d0);          // slots 0,1 for every group (d0 ≡ 0 mod 4):
    prefetch(d0 + 1);      // W1h/Xp in slots 2,3 stay intact through phase 1

    // ---- pack W1 -> W1h (k-pair fp16), X -> Xp ------------------------------
    for (int idx = tid; idx < 4096; idx += 384) {
        const int kp = idx >> 7, n = idx & 127;
        W1h[kp * W1H_STR + n] = packh2(W1[(size_t)(2 * kp) * 128 + n],
                                       W1[(size_t)(2 * kp + 1) * 128 + n]);
    }
    for (int idx = tid; idx < 4096; idx += 384) {
        const int row = idx >> 5, kp = idx & 31;
        const float2 v = *(const float2*)(xf + (size_t)(e0 + row) * 64 + 2 * kp);
        Xp[row * XP_STR + kp] = packh2(v.x, v.y);
    }
    if (tid < 128) b1s[tid] = b1[tid];
    if (tid < 64) { gs[tid] = gamma[tid]; bs[tid] = beta[tid]; }

    // ---- feats gather, pre-scaled by 1/sqrt(80) ----------------------------
    if (tid < 128) {
        const int e  = e0 + tid;
        const int di = ei[e];
        const int si = ei[E + e];
        const float* sr = res + (size_t)si * 56;
        const float* dr = res + (size_t)di * 56;
        const float inv80 = 0.111803398874989485f;            // 1/sqrt(80)
        const float i380  = 0.111803398874989485f * 0.57735026918962576f;
        const float s0 = esh[e * 4 + 0] * inv80;
        const float sx = esh[e * 4 + 1] * i380;
        const float sy = esh[e * 4 + 2] * i380;
        const float sz = esh[e * 4 + 3] * i380;
        float* fr = fs + tid * F_STR;
        #pragma unroll
        for (int j = 0; j < 32; j++) { fr[j] = sr[j] * s0; fr[32 + j] = dr[j] * s0; }
        #pragma unroll
        for (int m = 0; m < 8; m++) {
            fr[64 + m] = sr[32 + 3*m] * sx + sr[33 + 3*m] * sy + sr[34 + 3*m] * sz;
            fr[72 + m] = dr[32 + 3*m] * sx + dr[33 + 3*m] * sy + dr[34 + 3*m] * sz;
        }
    }
    __syncthreads();

    // ---- phase 1: H = relu(X @ W1 + b1) via MMA, pack into APu -------------
    if (w < 8) {
        const int mg2 = w & 3, nh = w >> 2;
        float Gp[2][8][4];
        #pragma unroll
        for (int ks = 0; ks < 4; ks++) {
            unsigned pa[2][4];
            #pragma unroll
            for (int mt = 0; mt < 2; mt++) {
                const int r0 = mg2 * 32 + mt * 16;
                pa[mt][0] = Xp[(r0 + g)     * XP_STR + ks * 8 + q];
                pa[mt][1] = Xp[(r0 + 8 + g) * XP_STR + ks * 8 + q];
                pa[mt][2] = Xp[(r0 + g)     * XP_STR + ks * 8 + 4 + q];
                pa[mt][3] = Xp[(r0 + 8 + g) * XP_STR + ks * 8 + 4 + q];
            }
            #pragma unroll
            for (int nt = 0; nt < 8; nt++) {
                const int n = nh * 64 + nt * 8 + g;
                const unsigned b0 = W1h[(ks * 8 + q)     * W1H_STR + n];
                const unsigned b1v = W1h[(ks * 8 + 4 + q) * W1H_STR + n];
                if (ks == 0) {
                    mma_f16_z(Gp[0][nt], pa[0], b0, b1v);
                    mma_f16_z(Gp[1][nt], pa[1], b0, b1v);
                } else {
                    mma_f16(Gp[0][nt], pa[0], b0, b1v);
                    mma_f16(Gp[1][nt], pa[1], b0, b1v);
                }
            }
        }
        #pragma unroll
        for (int mt = 0; mt < 2; mt++) {
            const int r0 = mg2 * 32 + mt * 16;
            #pragma unroll
            for (int nt = 0; nt < 8; nt++) {
                const int col = nh * 64 + nt * 8 + 2 * q;
                const int kp  = nh * 32 + nt * 4 + q;
                const float bl = b1s[col], bh = b1s[col + 1];
                APu[(r0 + g) * AP_STR + kp] =
                    packh2(fmaxf(Gp[mt][nt][0] + bl, 0.f),
                           fmaxf(Gp[mt][nt][1] + bh, 0.f));
                APu[(r0 + 8 + g) * AP_STR + kp] =
                    packh2(fmaxf(Gp[mt][nt][2] + bl, 0.f),
                           fmaxf(Gp[mt][nt][3] + bh, 0.f));
            }
        }
    }
    if (tid < 128) {     // augmented cols: kp64 = (1,0) for b2 row; kp65..71 = 0
        APu[tid * AP_STR + 64] = 0x00003C00u;
        #pragma unroll
        for (int kp = 65; kp < 72; kp++) APu[tid * AP_STR + kp] = 0u;
    }
    __syncthreads();     // APu ready; W1h/Xp (ring slots 2,3) dead from here

    // ---- load persistent A fragments (H, unscaled) -------------------------
    const int rb0 = mg * 32;
    unsigned afr[2][3][4];
    #pragma unroll
    for (int mt = 0; mt < 2; mt++)
        #pragma unroll
        for (int ks = 0; ks < 3; ks++) {
            const int K8 = (kt * 3 + ks) * 8;
            const int r0 = rb0 + mt * 16;
            afr[mt][ks][0] = APu[(r0 + g)     * AP_STR + K8 + q];
            afr[mt][ks][1] = APu[(r0 + 8 + g) * AP_STR + K8 + q];
            afr[mt][ks][2] = APu[(r0 + g)     * AP_STR + K8 + 4 + q];
            afr[mt][ks][3] = APu[(r0 + 8 + g) * AP_STR + K8 + 4 + q];
        }

    float acc[2][8][4];
    #pragma unroll
    for (int mt = 0; mt < 2; mt++)
        #pragma unroll
        for (int nt = 0; nt < 8; nt++)
            #pragma unroll
            for (int i = 0; i < 4; i++) acc[mt][nt][i] = 0.f;

    const int rowA0 = rb0 + g;
    const int barid = 1 + kt;

    // ---- main loop: 80 chunks in rotated order d = (d0 + i) mod 80 ---------
    #pragma unroll 1
    for (int i = 0; i < 80; i++) {
        if (i < 78) {
            int dp = d0 + i + 2; if (dp >= 80) dp -= 80;
            prefetch(dp);
            asm volatile("cp.async.wait_group 2;");
        } else if (i == 78) {
            asm volatile("cp.async.wait_group 1;");
        } else {
            asm volatile("cp.async.wait_group 0;");
        }
        asm volatile("bar.sync %0, %1;" :: "r"(barid), "r"(128) : "memory");

        int dk = d0 + i; if (dk >= 80) dk -= 80;
        const unsigned* Bb = BPu + (dk & 3) * BP_BUF;
        const float f00 = fs[(rowA0)      * F_STR + dk];
        const float f01 = fs[(rowA0 + 8)  * F_STR + dk];
        const float f10 = fs[(rowA0 + 16) * F_STR + dk];
        const float f11 = fs[(rowA0 + 24) * F_STR + dk];

        #pragma unroll
        for (int nt = 0; nt < 8; nt++) {
            const int n = nt * 8 + g;
            float G0[4], G1[4];
            {
                const unsigned b0 = Bb[(kt * 24 + q)     * BP_STR + n];
                const unsigned b1 = Bb[(kt * 24 + 4 + q) * BP_STR + n];
                mma_f16_z(G0, afr[0][0], b0, b1);
                mma_f16_z(G1, afr[1][0], b0, b1);
            }
            {
                const unsigned b0 = Bb[(kt * 24 + 8 + q)  * BP_STR + n];
                const unsigned b1 = Bb[(kt * 24 + 12 + q) * BP_STR + n];
                mma_f16(G0, afr[0][1], b0, b1);
                mma_f16(G1, afr[1][1], b0, b1);
            }
            {
                const unsigned b0 = Bb[(kt * 24 + 16 + q) * BP_STR + n];
                const unsigned b1 = Bb[(kt * 24 + 20 + q) * BP_STR + n];
                mma_f16(G0, afr[0][2], b0, b1);
                mma_f16(G1, afr[1][2], b0, b1);
            }
            acc[0][nt][0] = fmaf(f00, G0[0], acc[0][nt][0]);
            acc[0][nt][1] = fmaf(f00, G0[1], acc[0][nt][1]);
            acc[0][nt][2] = fmaf(f01, G0[2], acc[0][nt][2]);
            acc[0][nt][3] = fmaf(f01, G0[3], acc[0][nt][3]);
            acc[1][nt][0] = fmaf(f10, G1[0], acc[1][nt][0]);
            acc[1][nt][1] = fmaf(f10, G1[1], acc[1][nt][1]);
            acc[1][nt][2] = fmaf(f11, G1[2], acc[1][nt][2]);
            acc[1][nt][3] = fmaf(f11, G1[3], acc[1][nt][3]);
        }
    }
    __syncthreads();

    // ---- cross-warp (3-way k-split) reduction ------------------------------
    float* red = (float*)BPu;                    // ring dead
    if (kt >= 1) {
        float* dst = red + (kt - 1) * 8192 + mg * 2048;
        #pragma unroll
        for (int mt = 0; mt < 2; mt++)
            #pragma unroll
            for (int nt = 0; nt < 8; nt++)
                #pragma unroll
                for (int i = 0; i < 4; i++)
                    dst[(mt * 32 + nt * 4 + i) * 32 + lane] = acc[mt][nt][i];
    }
    __syncthreads();
    if (kt == 0) {
        const float* s1 = red + mg * 2048;
        const float* s2 = red + 8192 + mg * 2048;
        #pragma unroll
        for (int mt = 0; mt < 2; mt++)
            #pragma unroll
            for (int nt = 0; nt < 8; nt++)
                #pragma unroll
                for (int i = 0; i < 4; i++) {
                    const int off = (mt * 32 + nt * 4 + i) * 32 + lane;
                    acc[mt][nt][i] += s1[off] + s2[off];
                }

        // ---- epilogue: residual + LayerNorm (feats pre-scaled) -------------
        #pragma unroll
        for (int mt = 0; mt < 2; mt++) {
            #pragma unroll
            for (int par = 0; par < 2; par++) {
                const int r = rowA0 + mt * 16 + par * 8;
                const size_t rg = (size_t)(e0 + r);
                const float* xrow = xf + rg * 64;
                float v[16];
                float s = 0.f, ss = 0.f;
                #pragma unroll
                for (int nt = 0; nt < 8; nt++) {
                    const int h = nt * 8 + 2 * q;
                    const float2 xv = *(const float2*)(xrow + h);
                    const float v0 = acc[mt][nt][par * 2 + 0] + xv.x;
                    const float v1 = acc[mt][nt][par * 2 + 1] + xv.y;
                    v[nt * 2] = v0; v[nt * 2 + 1] = v1;
                    s += v0 + v1;
                    ss += v0 * v0 + v1 * v1;
                }
                s  += __shfl_xor_sync(0xffffffffu, s, 1);
                s  += __shfl_xor_sync(0xffffffffu, s, 2);
                ss += __shfl_xor_sync(0xffffffffu, ss, 1);
                ss += __shfl_xor_sync(0xffffffffu, ss, 2);
                const float mean = s * (1.f / 64.f);
                const float var  = ss * (1.f / 64.f) - mean * mean;
                const float rstd = rsqrtf(var + 1e-5f);
                float* orow = out + rg * 64;
                #pragma unroll
                for (int nt = 0; nt < 8; nt++) {
                    const int h = nt * 8 + 2 * q;
                    float2 o;
                    o.x = (v[nt * 2]     - mean) * rstd * gs[h]     + bs[h];
                    o.y = (v[nt * 2 + 1] - mean) * rstd * gs[h + 1] + bs[h + 1];
                    *(float2*)(orow + h) = o;
                }
            }
        }
    }
}

extern "C" void kernel_launch(void* const* d_in, const int* in_sizes, int n_in,
                              void* d_out, int out_size)
{
    const float* res   = (const float*)d_in[0];
    const float* xf    = (const float*)d_in[1];
    const float* esh   = (const float*)d_in[2];
    const float* W1    = (const float*)d_in[3];
    const float* b1    = (const float*)d_in[4];
    const float* W2    = (const float*)d_in[5];
    const float* b2    = (const float*)d_in[6];
    const float* gamma = (const float*)d_in[7];
    const float* beta  = (const float*)d_in[8];
    const int*   ei    = (const int*)d_in[9];   // int32: JAX x64-disabled

    const int E = in_sizes[1] / 64;             // edge_features is (E, 64)
    const size_t smem_bytes = SMEM_W * sizeof(float);

    cudaFuncSetAttribute(edge_kernel, cudaFuncAttributeMaxDynamicSharedMemorySize,
                         (int)smem_bytes);

    pack_w2<<<(80 * 72 * 64 + 255) / 256, 256>>>(W2, b2);
    edge_kernel<<<E / 128, 384, smem_bytes>>>(res, xf, esh, W1, b1,
                                              gamma, beta, ei, (float*)d_out, E);
}